// round 6
// baseline (speedup 1.0000x reference)
#include <cuda_runtime.h>
#include <cuda_bf16.h>
#include <cstdint>

// Problem constants
#define B_    4
#define C_    256
#define H_    64
#define W_    64
#define O_    256
#define KK_   9
#define HW_   4096
#define NPIX  16384
#define KTOT  2304
#define OMCH  27
#define OMSZ  (B_*OMCH*HW_)   // 442368
#define NCHUNK 8

// GEMM chunking: k' = kk*256 + c; 72 chunks of 32 channels
#define NCH   72
#define KPAD  40              // padded K row -> 80B rows, conflict-free ldmatrix/STS.128

// Device scratch
__device__ float  g_om[OMSZ];
__device__ float  g_om_part[NCHUNK * OMSZ];
// per chunk: [hi 256x40 bf16][lo 256x40 bf16] = 40960 B = 2560 float4
__device__ float4 g_wA[NCH * 2560];

// ---------------------------------------------------------------------------
// PTX helpers
// ---------------------------------------------------------------------------
__device__ __forceinline__ uint32_t s2u(const void* p) {
    uint32_t r;
    asm("{ .reg .u64 t; cvta.to.shared.u64 t, %1; cvt.u32.u64 %0, t; }" : "=r"(r) : "l"(p));
    return r;
}
__device__ __forceinline__ void ldsm4(uint32_t* r, uint32_t addr) {
    asm volatile("ldmatrix.sync.aligned.m8n8.x4.shared.b16 {%0,%1,%2,%3}, [%4];"
                 : "=r"(r[0]), "=r"(r[1]), "=r"(r[2]), "=r"(r[3]) : "r"(addr));
}
__device__ __forceinline__ void mma_bf16(float* d, const uint32_t* a, const uint32_t* b) {
    asm volatile(
        "mma.sync.aligned.m16n8k16.row.col.f32.bf16.bf16.f32 "
        "{%0,%1,%2,%3}, {%4,%5,%6,%7}, {%8,%9}, {%0,%1,%2,%3};"
        : "+f"(d[0]), "+f"(d[1]), "+f"(d[2]), "+f"(d[3])
        : "r"(a[0]), "r"(a[1]), "r"(a[2]), "r"(a[3]), "r"(b[0]), "r"(b[1]));
}
__device__ __forceinline__ void cp_async16(uint32_t dst, const void* src) {
    asm volatile("cp.async.cg.shared.global [%0], [%1], 16;" :: "r"(dst), "l"(src));
}
__device__ __forceinline__ void cp_commit() {
    asm volatile("cp.async.commit_group;" ::: "memory");
}
__device__ __forceinline__ void cp_wait0() {
    asm volatile("cp.async.wait_group 0;" ::: "memory");
}

// ---------------------------------------------------------------------------
// SMEM layout
// ---------------------------------------------------------------------------
#define SM_A     0        // 2 x 40960 (hi 20480 + lo 20480)
#define SM_B     81920    // 2 x 20480 (hi 10240 + lo 10240)
#define SM_IDXA  122880
#define SM_IDXB  127488
#define SM_WQ    132096
#define DYN_SMEM 150528

// ---------------------------------------------------------------------------
// Kernel 1: pack weights into bf16 hi/lo padded tiles
// ---------------------------------------------------------------------------
__global__ void prep_w_kernel(const float* __restrict__ weight) {
    int i = blockIdx.x * 256 + threadIdx.x;   // 0 .. 589823
    int chunk = i >> 13;
    int rem   = i & 8191;
    int o     = rem >> 5;
    int kl    = rem & 31;
    int kk = chunk >> 3;
    int cg = chunk & 7;
    int c  = cg * 32 + kl;
    float w = weight[o * KTOT + c * 9 + kk];
    __nv_bfloat16 hi = __float2bfloat16(w);
    __nv_bfloat16 lo = __float2bfloat16(w - __bfloat162float(hi));
    __nv_bfloat16* base = (__nv_bfloat16*)g_wA + (size_t)chunk * 20480;
    base[o * KPAD + kl]         = hi;
    base[10240 + o * KPAD + kl] = lo;
}

// ---------------------------------------------------------------------------
// Kernel 2: offset conv partials (unchanged)
// ---------------------------------------------------------------------------
__global__ __launch_bounds__(128) void offset_conv_kernel(
    const float* __restrict__ x, const float* __restrict__ w_off)
{
    __shared__ float s_w[OMCH * 288];
    const int t     = threadIdx.x;
    const int c0    = blockIdx.y * 32;
    const int pbase = blockIdx.x * 512;
    const int b     = pbase >> 12;

    for (int i = t; i < OMCH * 288; i += 128) {
        int j = i / 288, col = i - j * 288;
        s_w[i] = w_off[j * KTOT + c0 * 9 + col];
    }
    __syncthreads();

    int pimg[4], hh[4], ww[4];
#pragma unroll
    for (int p = 0; p < 4; p++) {
        int pix = pbase + t + (p << 7);
        pimg[p] = pix & 4095;
        hh[p] = pimg[p] >> 6;
        ww[p] = pimg[p] & 63;
    }

    float acc[OMCH][4];
#pragma unroll
    for (int j = 0; j < OMCH; j++)
#pragma unroll
        for (int p = 0; p < 4; p++) acc[j][p] = 0.f;

    const float* xb = x + (((size_t)b * C_ + c0) << 12);
    for (int cl = 0; cl < 32; cl++) {
        const float* xc = xb + ((size_t)cl << 12);
#pragma unroll
        for (int kh = 0; kh < 3; kh++) {
#pragma unroll
            for (int kw = 0; kw < 3; kw++) {
                float xv[4];
#pragma unroll
                for (int p = 0; p < 4; p++) {
                    int y  = hh[p] + kh - 1;
                    int xx = ww[p] + kw - 1;
                    bool ok = ((unsigned)y < 64u) && ((unsigned)xx < 64u);
                    xv[p] = ok ? __ldg(xc + (y << 6) + xx) : 0.f;
                }
                int wbase = cl * 9 + kh * 3 + kw;
#pragma unroll
                for (int j = 0; j < OMCH; j++) {
                    float wv = s_w[j * 288 + wbase];
#pragma unroll
                    for (int p = 0; p < 4; p++) acc[j][p] = fmaf(wv, xv[p], acc[j][p]);
                }
            }
        }
    }

    float* dst = g_om_part + (size_t)blockIdx.y * OMSZ + (((size_t)b * OMCH) << 12);
#pragma unroll
    for (int j = 0; j < OMCH; j++)
#pragma unroll
        for (int p = 0; p < 4; p++)
            dst[(j << 12) + pimg[p]] = acc[j][p];
}

__global__ void reduce_om_kernel(const float* __restrict__ b_off) {
    int i = blockIdx.x * 256 + threadIdx.x;
    float s = b_off[(i >> 12) % OMCH];
#pragma unroll
    for (int k = 0; k < NCHUNK; k++) s += g_om_part[(size_t)k * OMSZ + i];
    g_om[i] = s;
}

// ---------------------------------------------------------------------------
// Kernel 3: fused bilinear-sample + bf16 3-pass mma.sync GEMM, pipelined.
// 128 CTAs x 256 threads = 8 warps, warp tile 64x64, fragment caching:
//   per h: [Ah,Bh]->AhBh; [Al]->AlBh (Bh reused); [Bl over Bh]->AhBl (Ah reused)
// ---------------------------------------------------------------------------
struct GatherCtx {
    int i00, i01, i10, i11;
    float4 wq;
    const float* xch;
};

__device__ __forceinline__ void gather_issue(const GatherCtx& g, int grp, float* r) {
    const float* xc0 = g.xch + ((size_t)(2 * grp) << 12);
    const float* xc1 = xc0 + 4096;
    r[0] = __ldg(xc0 + g.i00); r[1] = __ldg(xc0 + g.i01);
    r[2] = __ldg(xc0 + g.i10); r[3] = __ldg(xc0 + g.i11);
    r[4] = __ldg(xc1 + g.i00); r[5] = __ldg(xc1 + g.i01);
    r[6] = __ldg(xc1 + g.i10); r[7] = __ldg(xc1 + g.i11);
}
__device__ __forceinline__ void gather_combine(const GatherCtx& g, const float* r,
                                               float& v0, float& v1) {
    v0 = g.wq.x * r[0] + g.wq.y * r[1] + g.wq.z * r[2] + g.wq.w * r[3];
    v1 = g.wq.x * r[4] + g.wq.y * r[5] + g.wq.z * r[6] + g.wq.w * r[7];
}

__global__ __launch_bounds__(256, 1) void dcn_mma_kernel(
    const float* __restrict__ x, const float* __restrict__ bias,
    float* __restrict__ out)
{
    extern __shared__ char smem[];
    uint32_t sb = s2u(smem);

    const int t    = threadIdx.x;
    const int lane = t & 31;
    const int wid  = t >> 5;
    const int mw   = wid >> 1;     // 0..3 -> rows mw*64..
    const int nw   = wid & 1;      // 0..1 -> cols nw*64..
    const int pbase = blockIdx.x * 128;
    const int b     = pbase >> 12;
    const int pib   = pbase & 4095;

    uint32_t* s_idxA = (uint32_t*)(smem + SM_IDXA);
    uint32_t* s_idxB = (uint32_t*)(smem + SM_IDXB);
    float4*   s_wq   = (float4*)(smem + SM_WQ);

    // ---- sampling params: 9 kk x 128 pixels ----
    for (int e = t; e < KK_ * 128; e += 256) {
        int kk = e >> 7;
        int n  = e & 127;
        int pimg = pib + n;
        int h = pimg >> 6, w = pimg & 63;
        const float* omb = g_om + (((size_t)b * OMCH) << 12) + pimg;
        float dy = omb[(size_t)(2 * kk) << 12];
        float dx = omb[(size_t)(2 * kk + 1) << 12];
        float mv = omb[(size_t)(18 + kk) << 12];
        float m  = 1.0f / (1.0f + expf(-mv));
        int kh = kk / 3, kw = kk - 3 * kh;
        float py = (float)(h - 1 + kh) + dy;
        float px = (float)(w - 1 + kw) + dx;
        float y0f = floorf(py), x0f = floorf(px);
        float ly = py - y0f, lx = px - x0f;
        int y0 = (int)y0f, x0 = (int)x0f;
        int y1 = y0 + 1, x1 = x0 + 1;
        float vy0 = ((unsigned)y0 < 64u) ? 1.f : 0.f;
        float vy1 = ((unsigned)y1 < 64u) ? 1.f : 0.f;
        float vx0 = ((unsigned)x0 < 64u) ? 1.f : 0.f;
        float vx1 = ((unsigned)x1 < 64u) ? 1.f : 0.f;
        int y0c = min(max(y0, 0), 63), y1c = min(max(y1, 0), 63);
        int x0c = min(max(x0, 0), 63), x1c = min(max(x1, 0), 63);
        float w00 = (1.f - ly) * (1.f - lx) * m * vy0 * vx0;
        float w01 = (1.f - ly) * lx * m * vy0 * vx1;
        float w10 = ly * (1.f - lx) * m * vy1 * vx0;
        float w11 = ly * lx * m * vy1 * vx1;
        s_idxA[e] = (uint32_t)(y0c * 64 + x0c) | ((uint32_t)(y0c * 64 + x1c) << 16);
        s_idxB[e] = (uint32_t)(y1c * 64 + x0c) | ((uint32_t)(y1c * 64 + x1c) << 16);
        s_wq[e] = make_float4(w00, w01, w10, w11);
    }
    __syncthreads();

    float acc[4][8][4];
#pragma unroll
    for (int i = 0; i < 4; i++)
#pragma unroll
        for (int j = 0; j < 8; j++)
#pragma unroll
            for (int q = 0; q < 4; q++) acc[i][j][q] = 0.f;

    const uint32_t a_off = (uint32_t)((lane & 15) * 80 + ((lane >> 4) << 4));
    const uint32_t b_off = (uint32_t)((((lane >> 4) << 3) + (lane & 7)) * 80
                                      + (((lane >> 3) & 1) << 4));

    const float* xb = x + ((size_t)b << 20);
    const int nloc  = t & 127;     // pixel this thread produces
    const int klq   = t >> 7;      // 0/1: 16-channel half

    auto load_ctx = [&](int c, GatherCtx& g) {
        int kk = c >> 3, cg = c & 7;
        int e  = (kk << 7) + nloc;
        uint32_t ia = s_idxA[e], ib2 = s_idxB[e];
        g.i00 = ia & 0xffff;  g.i01 = ia >> 16;
        g.i10 = ib2 & 0xffff; g.i11 = ib2 >> 16;
        g.wq  = s_wq[e];
        g.xch = xb + ((size_t)(cg * 32 + klq * 16) << 12);
    };

    auto loadA = [&](uint32_t base, int h, uint32_t (*f)[4]) {
#pragma unroll
        for (int mi = 0; mi < 4; mi++)
            ldsm4(f[mi], base + a_off + (uint32_t)((mw * 64 + mi * 16) * 80 + h * 32));
    };
    auto loadB = [&](uint32_t base, int h, uint32_t (*f)[4]) {
#pragma unroll
        for (int p = 0; p < 4; p++)
            ldsm4(f[p], base + b_off + (uint32_t)((nw * 64 + p * 16) * 80 + h * 32));
    };
    auto mma_block = [&](uint32_t (*af)[4], uint32_t (*bf)[4]) {
#pragma unroll
        for (int mi = 0; mi < 4; mi++)
#pragma unroll
            for (int p = 0; p < 4; p++) {
                mma_bf16(acc[mi][2 * p],     af[mi], &bf[p][0]);
                mma_bf16(acc[mi][2 * p + 1], af[mi], &bf[p][2]);
            }
    };

    uint32_t ph[8], pl[8];
    auto pack = [&](const float* v) {
#pragma unroll
        for (int q = 0; q < 8; q++) {
            uint32_t ua = __float_as_uint(v[2 * q]);
            uint32_t ub = __float_as_uint(v[2 * q + 1]);
            float ta = __uint_as_float(ua & 0xffff0000u);
            float tb = __uint_as_float(ub & 0xffff0000u);
            ph[q] = __byte_perm(ua, ub, 0x7632);
            pl[q] = __byte_perm(__float_as_uint(v[2 * q] - ta),
                                __float_as_uint(v[2 * q + 1] - tb), 0x7632);
        }
    };

    // ---- prologue: A(0) cp.async + B(0) gathered ----
    {
        const float4* srcA = g_wA;
        uint32_t dA = sb + SM_A;
#pragma unroll
        for (int r = 0; r < 10; r++)
            cp_async16(dA + (uint32_t)((t + (r << 8)) << 4), srcA + t + (r << 8));
        cp_commit();

        GatherCtx g; load_ctx(0, g);
        float v[16], r[8];
#pragma unroll
        for (int grp = 0; grp < 8; grp++) {
            gather_issue(g, grp, r);
            gather_combine(g, r, v[2 * grp], v[2 * grp + 1]);
        }
        pack(v);
    }

    const uint32_t bstore = (uint32_t)(nloc * 80 + klq * 32);

    for (int c = 0; c < NCH; c++) {
        const int buf = c & 1;

        // ---- STS B(c): 4x STS.128 conflict-free ----
        {
            char* bh = smem + SM_B + buf * 20480 + bstore;
            *(float4*)bh                  = *(float4*)(ph + 0);
            *(float4*)(bh + 16)           = *(float4*)(ph + 4);
            *(float4*)(bh + 10240)        = *(float4*)(pl + 0);
            *(float4*)(bh + 10240 + 16)   = *(float4*)(pl + 4);
        }
        cp_wait0();
        __syncthreads();

        const bool pf = (c + 1 < NCH);
        if (pf) {
            const float4* srcA = g_wA + (size_t)(c + 1) * 2560;
            uint32_t dA = sb + SM_A + (buf ^ 1) * 40960;
#pragma unroll
            for (int r = 0; r < 10; r++)
                cp_async16(dA + (uint32_t)((t + (r << 8)) << 4), srcA + t + (r << 8));
            cp_commit();
        }

        GatherCtx g;
        if (pf) load_ctx(c + 1, g);

        const uint32_t Ah0 = sb + SM_A + buf * 40960;
        const uint32_t Al0 = Ah0 + 20480;
        const uint32_t Bh0 = sb + SM_B + buf * 20480;
        const uint32_t Bl0 = Bh0 + 10240;

        float v[16], r0[8], r1[8];
        uint32_t afh[4][4], afl[4][4], bf[4][4];

        if (pf) { gather_issue(g, 0, r0); gather_issue(g, 1, r1); }

        // h = 0
        loadA(Ah0, 0, afh); loadB(Bh0, 0, bf);
        mma_block(afh, bf);
        if (pf) { gather_combine(g, r0, v[0], v[1]); gather_issue(g, 2, r0); }
        loadA(Al0, 0, afl);
        mma_block(afl, bf);
        if (pf) { gather_combine(g, r1, v[2], v[3]); gather_issue(g, 3, r1); }
        loadB(Bl0, 0, bf);
        mma_block(afh, bf);
        if (pf) { gather_combine(g, r0, v[4], v[5]); gather_issue(g, 4, r0); }

        // h = 1
        loadA(Ah0, 1, afh); loadB(Bh0, 1, bf);
        mma_block(afh, bf);
        if (pf) { gather_combine(g, r1, v[6], v[7]); gather_issue(g, 5, r1); }
        loadA(Al0, 1, afl);
        mma_block(afl, bf);
        if (pf) { gather_combine(g, r0, v[8], v[9]); gather_issue(g, 6, r0); }
        loadB(Bl0, 1, bf);
        mma_block(afh, bf);
        if (pf) {
            gather_combine(g, r1, v[10], v[11]);
            gather_issue(g, 7, r1);
            gather_combine(g, r0, v[12], v[13]);
            gather_combine(g, r1, v[14], v[15]);
            pack(v);
        }
    }

    // ---- epilogue: bias + store ----
#pragma unroll
    for (int mi = 0; mi < 4; mi++) {
        int o0 = mw * 64 + mi * 16 + (lane >> 2);
        float bv0 = __ldg(bias + o0);
        float bv1 = __ldg(bias + o0 + 8);
        float* r0p = out + (((size_t)(b * O_ + o0)) << 12) + pib;
        float* r1p = r0p + (8 << 12);
#pragma unroll
        for (int nj = 0; nj < 8; nj++) {
            int cc = nw * 64 + nj * 8 + ((lane & 3) << 1);
            float2 v0 = make_float2(acc[mi][nj][0] + bv0, acc[mi][nj][1] + bv0);
            float2 v1 = make_float2(acc[mi][nj][2] + bv1, acc[mi][nj][3] + bv1);
            *(float2*)(r0p + cc) = v0;
            *(float2*)(r1p + cc) = v1;
        }
    }
}

// ---------------------------------------------------------------------------
// Launch
// ---------------------------------------------------------------------------
extern "C" void kernel_launch(void* const* d_in, const int* in_sizes, int n_in,
                              void* d_out, int out_size)
{
    const float* x      = (const float*)d_in[0];
    const float* w_off  = (const float*)d_in[1];
    const float* b_off  = (const float*)d_in[2];
    const float* weight = (const float*)d_in[3];
    const float* bias   = (const float*)d_in[4];
    float* out = (float*)d_out;

    cudaFuncSetAttribute(dcn_mma_kernel,
                         cudaFuncAttributeMaxDynamicSharedMemorySize, DYN_SMEM);

    prep_w_kernel<<<2304, 256>>>(weight);
    offset_conv_kernel<<<dim3(32, NCHUNK), 128>>>(x, w_off);
    reduce_om_kernel<<<OMSZ / 256, 256>>>(b_off);
    dcn_mma_kernel<<<NPIX / 128, 256, DYN_SMEM>>>(x, bias, out);
}

// round 8
// speedup vs baseline: 1.0580x; 1.0580x over previous
#include <cuda_runtime.h>
#include <cuda_bf16.h>
#include <cstdint>

// Problem constants
#define B_    4
#define C_    256
#define H_    64
#define W_    64
#define O_    256
#define KK_   9
#define HW_   4096
#define NPIX  16384
#define KTOT  2304
#define OMCH  27
#define OMSZ  (B_*OMCH*HW_)   // 442368
#define NCHUNK 8

// GEMM chunking: k' = kk*256 + c; 72 chunks of 32 channels
#define NCH   72
#define KPAD  40              // padded K row -> 80B rows, conflict-free ldmatrix/STS.128

// Device scratch
__device__ float  g_om[OMSZ];
__device__ float  g_om_part[NCHUNK * OMSZ];
// per chunk: [hi 256x40 bf16][lo 256x40 bf16] = 40960 B = 2560 float4
__device__ float4 g_wA[NCH * 2560];

// ---------------------------------------------------------------------------
// PTX helpers
// ---------------------------------------------------------------------------
__device__ __forceinline__ uint32_t s2u(const void* p) {
    uint32_t r;
    asm("{ .reg .u64 t; cvta.to.shared.u64 t, %1; cvt.u32.u64 %0, t; }" : "=r"(r) : "l"(p));
    return r;
}
__device__ __forceinline__ void ldsm4(uint32_t* r, uint32_t addr) {
    asm volatile("ldmatrix.sync.aligned.m8n8.x4.shared.b16 {%0,%1,%2,%3}, [%4];"
                 : "=r"(r[0]), "=r"(r[1]), "=r"(r[2]), "=r"(r[3]) : "r"(addr));
}
__device__ __forceinline__ void mma_bf16(float* d, const uint32_t* a, const uint32_t* b) {
    asm volatile(
        "mma.sync.aligned.m16n8k16.row.col.f32.bf16.bf16.f32 "
        "{%0,%1,%2,%3}, {%4,%5,%6,%7}, {%8,%9}, {%0,%1,%2,%3};"
        : "+f"(d[0]), "+f"(d[1]), "+f"(d[2]), "+f"(d[3])
        : "r"(a[0]), "r"(a[1]), "r"(a[2]), "r"(a[3]), "r"(b[0]), "r"(b[1]));
}
__device__ __forceinline__ void cp_async16(uint32_t dst, const void* src) {
    asm volatile("cp.async.cg.shared.global [%0], [%1], 16;" :: "r"(dst), "l"(src));
}
__device__ __forceinline__ void cp_commit() {
    asm volatile("cp.async.commit_group;" ::: "memory");
}
__device__ __forceinline__ void cp_wait0() {
    asm volatile("cp.async.wait_group 0;" ::: "memory");
}
__device__ __forceinline__ void cp_wait1() {
    asm volatile("cp.async.wait_group 1;" ::: "memory");
}

// ---------------------------------------------------------------------------
// SMEM layout: A ring x3, B ring x3, params
// ---------------------------------------------------------------------------
#define SM_A     0        // 3 x 40960 (hi 20480 + lo 20480) = 122880
#define SM_B     122880   // 3 x 20480 (hi 10240 + lo 10240) = 61440
#define SM_IDXA  184320   // 1152 u32
#define SM_IDXB  188928   // 1152 u32
#define SM_WQ    193536   // 1152 float4
#define DYN_SMEM 211968

// ---------------------------------------------------------------------------
// Kernel 1: pack weights into bf16 hi/lo padded tiles
// ---------------------------------------------------------------------------
__global__ void prep_w_kernel(const float* __restrict__ weight) {
    int i = blockIdx.x * 256 + threadIdx.x;   // 0 .. 589823
    int chunk = i >> 13;
    int rem   = i & 8191;
    int o     = rem >> 5;
    int kl    = rem & 31;
    int kk = chunk >> 3;
    int cg = chunk & 7;
    int c  = cg * 32 + kl;
    float w = weight[o * KTOT + c * 9 + kk];
    __nv_bfloat16 hi = __float2bfloat16(w);
    __nv_bfloat16 lo = __float2bfloat16(w - __bfloat162float(hi));
    __nv_bfloat16* base = (__nv_bfloat16*)g_wA + (size_t)chunk * 20480;
    base[o * KPAD + kl]         = hi;
    base[10240 + o * KPAD + kl] = lo;
}

// ---------------------------------------------------------------------------
// Kernel 2: offset conv partials (unchanged)
// ---------------------------------------------------------------------------
__global__ __launch_bounds__(128) void offset_conv_kernel(
    const float* __restrict__ x, const float* __restrict__ w_off)
{
    __shared__ float s_w[OMCH * 288];
    const int t     = threadIdx.x;
    const int c0    = blockIdx.y * 32;
    const int pbase = blockIdx.x * 512;
    const int b     = pbase >> 12;

    for (int i = t; i < OMCH * 288; i += 128) {
        int j = i / 288, col = i - j * 288;
        s_w[i] = w_off[j * KTOT + c0 * 9 + col];
    }
    __syncthreads();

    int pimg[4], hh[4], ww[4];
#pragma unroll
    for (int p = 0; p < 4; p++) {
        int pix = pbase + t + (p << 7);
        pimg[p] = pix & 4095;
        hh[p] = pimg[p] >> 6;
        ww[p] = pimg[p] & 63;
    }

    float acc[OMCH][4];
#pragma unroll
    for (int j = 0; j < OMCH; j++)
#pragma unroll
        for (int p = 0; p < 4; p++) acc[j][p] = 0.f;

    const float* xb = x + (((size_t)b * C_ + c0) << 12);
    for (int cl = 0; cl < 32; cl++) {
        const float* xc = xb + ((size_t)cl << 12);
#pragma unroll
        for (int kh = 0; kh < 3; kh++) {
#pragma unroll
            for (int kw = 0; kw < 3; kw++) {
                float xv[4];
#pragma unroll
                for (int p = 0; p < 4; p++) {
                    int y  = hh[p] + kh - 1;
                    int xx = ww[p] + kw - 1;
                    bool ok = ((unsigned)y < 64u) && ((unsigned)xx < 64u);
                    xv[p] = ok ? __ldg(xc + (y << 6) + xx) : 0.f;
                }
                int wbase = cl * 9 + kh * 3 + kw;
#pragma unroll
                for (int j = 0; j < OMCH; j++) {
                    float wv = s_w[j * 288 + wbase];
#pragma unroll
                    for (int p = 0; p < 4; p++) acc[j][p] = fmaf(wv, xv[p], acc[j][p]);
                }
            }
        }
    }

    float* dst = g_om_part + (size_t)blockIdx.y * OMSZ + (((size_t)b * OMCH) << 12);
#pragma unroll
    for (int j = 0; j < OMCH; j++)
#pragma unroll
        for (int p = 0; p < 4; p++)
            dst[(j << 12) + pimg[p]] = acc[j][p];
}

__global__ void reduce_om_kernel(const float* __restrict__ b_off) {
    int i = blockIdx.x * 256 + threadIdx.x;
    float s = b_off[(i >> 12) % OMCH];
#pragma unroll
    for (int k = 0; k < NCHUNK; k++) s += g_om_part[(size_t)k * OMSZ + i];
    g_om[i] = s;
}

// ---------------------------------------------------------------------------
// Kernel 3: fused bilinear-sample + bf16 3-pass mma.sync GEMM.
// 128 CTAs x 512 threads = 16 warps (4 M x 4 N, warp tile 64x32).
// Triple-buffered A (cp.async, depth-1 wait) and B (gather+STS mid-burst):
// the inter-chunk critical path is barrier -> ldsm -> tensor-paced burst.
// ---------------------------------------------------------------------------
struct GatherCtx {
    int i00, i01, i10, i11;
    float4 wq;
    const float* xch;   // channel base for this thread (klq*8)
};

__device__ __forceinline__ void gather_issue(const GatherCtx& g, int grp, float* r) {
    const float* xc0 = g.xch + ((size_t)(2 * grp) << 12);
    const float* xc1 = xc0 + 4096;
    r[0] = __ldg(xc0 + g.i00); r[1] = __ldg(xc0 + g.i01);
    r[2] = __ldg(xc0 + g.i10); r[3] = __ldg(xc0 + g.i11);
    r[4] = __ldg(xc1 + g.i00); r[5] = __ldg(xc1 + g.i01);
    r[6] = __ldg(xc1 + g.i10); r[7] = __ldg(xc1 + g.i11);
}
__device__ __forceinline__ void gather_combine(const GatherCtx& g, const float* r,
                                               float& v0, float& v1) {
    v0 = g.wq.x * r[0] + g.wq.y * r[1] + g.wq.z * r[2] + g.wq.w * r[3];
    v1 = g.wq.x * r[4] + g.wq.y * r[5] + g.wq.z * r[6] + g.wq.w * r[7];
}
__device__ __forceinline__ void pack4(const float* v, uint32_t* ph, uint32_t* pl) {
#pragma unroll
    for (int q = 0; q < 4; q++) {
        uint32_t ua = __float_as_uint(v[2 * q]);
        uint32_t ub = __float_as_uint(v[2 * q + 1]);
        float ta = __uint_as_float(ua & 0xffff0000u);
        float tb = __uint_as_float(ub & 0xffff0000u);
        ph[q] = __byte_perm(ua, ub, 0x7632);
        pl[q] = __byte_perm(__float_as_uint(v[2 * q] - ta),
                            __float_as_uint(v[2 * q + 1] - tb), 0x7632);
    }
}

__device__ __forceinline__ void mma_subpass(uint32_t Ab, uint32_t Bb,
                                            uint32_t a_off, uint32_t b_off,
                                            int mw, int nw, int h,
                                            float (*acc)[4][4]) {
    uint32_t af[4][4], bfr[2][4];
#pragma unroll
    for (int mi = 0; mi < 4; mi++)
        ldsm4(af[mi], Ab + a_off + (uint32_t)((mw * 64 + mi * 16) * 80 + h * 32));
#pragma unroll
    for (int p = 0; p < 2; p++)
        ldsm4(bfr[p], Bb + b_off + (uint32_t)((nw * 32 + p * 16) * 80 + h * 32));
#pragma unroll
    for (int mi = 0; mi < 4; mi++)
#pragma unroll
        for (int p = 0; p < 2; p++) {
            mma_bf16(acc[mi][2 * p],     af[mi], &bfr[p][0]);
            mma_bf16(acc[mi][2 * p + 1], af[mi], &bfr[p][2]);
        }
}

__global__ __launch_bounds__(512, 1) void dcn_mma_kernel(
    const float* __restrict__ x, const float* __restrict__ bias,
    float* __restrict__ out)
{
    extern __shared__ char smem[];
    uint32_t sb = s2u(smem);

    const int t    = threadIdx.x;
    const int lane = t & 31;
    const int wid  = t >> 5;
    const int mw   = wid >> 2;
    const int nw   = wid & 3;
    const int pbase = blockIdx.x * 128;
    const int b     = pbase >> 12;
    const int pib   = pbase & 4095;

    uint32_t* s_idxA = (uint32_t*)(smem + SM_IDXA);
    uint32_t* s_idxB = (uint32_t*)(smem + SM_IDXB);
    float4*   s_wq   = (float4*)(smem + SM_WQ);

    // ---- sampling params: 9 kk x 128 pixels ----
    for (int e = t; e < KK_ * 128; e += 512) {
        int kk = e >> 7;
        int n  = e & 127;
        int pimg = pib + n;
        int h = pimg >> 6, w = pimg & 63;
        const float* omb = g_om + (((size_t)b * OMCH) << 12) + pimg;
        float dy = omb[(size_t)(2 * kk) << 12];
        float dx = omb[(size_t)(2 * kk + 1) << 12];
        float mv = omb[(size_t)(18 + kk) << 12];
        float m  = 1.0f / (1.0f + expf(-mv));
        int kh = kk / 3, kw = kk - 3 * kh;
        float py = (float)(h - 1 + kh) + dy;
        float px = (float)(w - 1 + kw) + dx;
        float y0f = floorf(py), x0f = floorf(px);
        float ly = py - y0f, lx = px - x0f;
        int y0 = (int)y0f, x0 = (int)x0f;
        int y1 = y0 + 1, x1 = x0 + 1;
        float vy0 = ((unsigned)y0 < 64u) ? 1.f : 0.f;
        float vy1 = ((unsigned)y1 < 64u) ? 1.f : 0.f;
        float vx0 = ((unsigned)x0 < 64u) ? 1.f : 0.f;
        float vx1 = ((unsigned)x1 < 64u) ? 1.f : 0.f;
        int y0c = min(max(y0, 0), 63), y1c = min(max(y1, 0), 63);
        int x0c = min(max(x0, 0), 63), x1c = min(max(x1, 0), 63);
        float w00 = (1.f - ly) * (1.f - lx) * m * vy0 * vx0;
        float w01 = (1.f - ly) * lx * m * vy0 * vx1;
        float w10 = ly * (1.f - lx) * m * vy1 * vx0;
        float w11 = ly * lx * m * vy1 * vx1;
        s_idxA[e] = (uint32_t)(y0c * 64 + x0c) | ((uint32_t)(y0c * 64 + x1c) << 16);
        s_idxB[e] = (uint32_t)(y1c * 64 + x0c) | ((uint32_t)(y1c * 64 + x1c) << 16);
        s_wq[e] = make_float4(w00, w01, w10, w11);
    }

    float acc[4][4][4];
#pragma unroll
    for (int i = 0; i < 4; i++)
#pragma unroll
        for (int j = 0; j < 4; j++)
#pragma unroll
            for (int q = 0; q < 4; q++) acc[i][j][q] = 0.f;

    const uint32_t a_off = (uint32_t)((lane & 15) * 80 + ((lane >> 4) << 4));
    const uint32_t b_off = (uint32_t)((((lane >> 4) << 3) + (lane & 7)) * 80
                                      + (((lane >> 3) & 1) << 4));

    const float* xb = x + ((size_t)b << 20);
    const int nloc  = t & 127;     // pixel this thread produces
    const int klq   = t >> 7;      // channel octet: kl = klq*8 + j

    auto load_ctx = [&](int c, GatherCtx& g) {
        int kk = c >> 3, cg = c & 7;
        int e  = (kk << 7) + nloc;
        uint32_t ia = s_idxA[e], ib2 = s_idxB[e];
        g.i00 = ia & 0xffff;  g.i01 = ia >> 16;
        g.i10 = ib2 & 0xffff; g.i11 = ib2 >> 16;
        g.wq  = s_wq[e];
        g.xch = xb + ((size_t)(cg * 32 + klq * 8) << 12);
    };

    const uint32_t bstore = (uint32_t)(nloc * 80 + klq * 16);

    // ---- prologue: A(0), A(1) via cp.async; gather+STS B(0) ----
    {
        const float4* srcA0 = g_wA;
        uint32_t dA0 = sb + SM_A;
#pragma unroll
        for (int r = 0; r < 5; r++)
            cp_async16(dA0 + (uint32_t)((t + (r << 9)) << 4), srcA0 + t + (r << 9));
        cp_commit();
        const float4* srcA1 = g_wA + 2560;
        uint32_t dA1 = sb + SM_A + 40960;
#pragma unroll
        for (int r = 0; r < 5; r++)
            cp_async16(dA1 + (uint32_t)((t + (r << 9)) << 4), srcA1 + t + (r << 9));
        cp_commit();

        __syncthreads();   // params visible before gather ctx reads

        GatherCtx g; load_ctx(0, g);
        float v[8], r[8];
#pragma unroll
        for (int grp = 0; grp < 4; grp++) {
            gather_issue(g, grp, r);
            gather_combine(g, r, v[2 * grp], v[2 * grp + 1]);
        }
        uint32_t ph[4], pl[4];
        pack4(v, ph, pl);
        char* bh = smem + SM_B + bstore;
        *(float4*)bh           = *(float4*)ph;
        *(float4*)(bh + 10240) = *(float4*)pl;

        cp_wait1();          // A(0) resident (A(1) may be in flight)
        __syncthreads();
    }

    int cb = 0;   // ring buffer index of chunk c
    for (int c = 0; c < NCH; c++) {
        const int nb = (cb == 2) ? 0 : cb + 1;   // buf of c+1
        const int pb = (nb == 2) ? 0 : nb + 1;   // buf of c+2

        const uint32_t Ah0 = sb + SM_A + cb * 40960;
        const uint32_t Al0 = Ah0 + 20480;
        const uint32_t Bh0 = sb + SM_B + cb * 20480;
        const uint32_t Bl0 = Bh0 + 10240;

        const bool pf = (c + 1 < NCH);
        GatherCtx g;
        float v[8], r[8];
        if (pf) { load_ctx(c + 1, g); gather_issue(g, 0, r); }

        mma_subpass(Ah0, Bh0, a_off, b_off, mw, nw, 0, acc);
        if (pf) { gather_combine(g, r, v[0], v[1]); gather_issue(g, 1, r); }
        mma_subpass(Ah0, Bh0, a_off, b_off, mw, nw, 1, acc);
        if (pf) { gather_combine(g, r, v[2], v[3]); gather_issue(g, 2, r); }
        mma_subpass(Ah0, Bl0, a_off, b_off, mw, nw, 0, acc);
        if (pf) { gather_combine(g, r, v[4], v[5]); gather_issue(g, 3, r); }
        mma_subpass(Ah0, Bl0, a_off, b_off, mw, nw, 1, acc);
        if (pf) {
            gather_combine(g, r, v[6], v[7]);
            uint32_t ph[4], pl[4];
            pack4(v, ph, pl);
            // STS B(c+1) mid-burst into ring slot nb (consumers 2 barriers past)
            char* bh = smem + SM_B + nb * 20480 + bstore;
            *(float4*)bh           = *(float4*)ph;
            *(float4*)(bh + 10240) = *(float4*)pl;
        }
        if (c + 2 < NCH) {
            const float4* srcA = g_wA + (size_t)(c + 2) * 2560;
            uint32_t dA = sb + SM_A + pb * 40960;
#pragma unroll
            for (int rr = 0; rr < 5; rr++)
                cp_async16(dA + (uint32_t)((t + (rr << 9)) << 4), srcA + t + (rr << 9));
            cp_commit();
        }
        mma_subpass(Al0, Bh0, a_off, b_off, mw, nw, 0, acc);
        mma_subpass(Al0, Bh0, a_off, b_off, mw, nw, 1, acc);

        if (c + 2 < NCH) cp_wait1();   // A(c+1) done, A(c+2) may fly
        else             cp_wait0();   // tail: drain everything
        __syncthreads();
        cb = nb;
    }

    // ---- epilogue: bias + store ----
    const int m0   = mw * 64 + (lane >> 2);
    const int col0 = nw * 32 + ((lane & 3) << 1);
#pragma unroll
    for (int mi = 0; mi < 4; mi++) {
        int o = m0 + mi * 16;
        float bv0 = __ldg(bias + o);
        float bv1 = __ldg(bias + o + 8);
        float* r0 = out + (((size_t)(b * O_ + o)) << 12) + pib;
        float* r1 = r0 + (8 << 12);
#pragma unroll
        for (int nj = 0; nj < 4; nj++) {
            int cc = col0 + nj * 8;
            float2 v0 = make_float2(acc[mi][nj][0] + bv0, acc[mi][nj][1] + bv0);
            float2 v1 = make_float2(acc[mi][nj][2] + bv1, acc[mi][nj][3] + bv1);
            *(float2*)(r0 + cc) = v0;
            *(float2*)(r1 + cc) = v1;
        }
    }
}

// ---------------------------------------------------------------------------
// Launch
// ---------------------------------------------------------------------------
extern "C" void kernel_launch(void* const* d_in, const int* in_sizes, int n_in,
                              void* d_out, int out_size)
{
    const float* x      = (const float*)d_in[0];
    const float* w_off  = (const float*)d_in[1];
    const float* b_off  = (const float*)d_in[2];
    const float* weight = (const float*)d_in[3];
    const float* bias   = (const float*)d_in[4];
    float* out = (float*)d_out;

    cudaFuncSetAttribute(dcn_mma_kernel,
                         cudaFuncAttributeMaxDynamicSharedMemorySize, DYN_SMEM);

    prep_w_kernel<<<2304, 256>>>(weight);
    offset_conv_kernel<<<dim3(32, NCHUNK), 128>>>(x, w_off);
    reduce_om_kernel<<<OMSZ / 256, 256>>>(b_off);
    dcn_mma_kernel<<<NPIX / 128, 512, DYN_SMEM>>>(x, bias, out);
}

// round 9
// speedup vs baseline: 1.2052x; 1.1391x over previous
#include <cuda_runtime.h>
#include <cuda_bf16.h>
#include <cstdint>

// Problem constants
#define B_    4
#define C_    256
#define H_    64
#define W_    64
#define O_    256
#define KK_   9
#define HW_   4096
#define NPIX  16384
#define KTOT  2304
#define OMCH  27
#define OMSZ  (B_*OMCH*HW_)   // 442368

// GEMM chunking: k' = kk*256 + c; 72 chunks of 32 channels
#define NCH   72
#define KPAD  40              // padded K row -> 80B rows, conflict-free ldmatrix/STS.128

// Device scratch
__device__ float  g_om[OMSZ];
// main GEMM weights: per chunk [hi 256x40 bf16][lo 256x40 bf16] = 40960 B
__device__ float4 g_wA[NCH * 2560];
// offset-conv weights: per chunk [hi 32x40 bf16][lo 32x40 bf16] = 5120 B
__device__ __nv_bfloat16 g_wOff[NCH * 2560];

// ---------------------------------------------------------------------------
// PTX helpers
// ---------------------------------------------------------------------------
__device__ __forceinline__ uint32_t s2u(const void* p) {
    uint32_t r;
    asm("{ .reg .u64 t; cvta.to.shared.u64 t, %1; cvt.u32.u64 %0, t; }" : "=r"(r) : "l"(p));
    return r;
}
__device__ __forceinline__ void ldsm4(uint32_t* r, uint32_t addr) {
    asm volatile("ldmatrix.sync.aligned.m8n8.x4.shared.b16 {%0,%1,%2,%3}, [%4];"
                 : "=r"(r[0]), "=r"(r[1]), "=r"(r[2]), "=r"(r[3]) : "r"(addr));
}
__device__ __forceinline__ void mma_bf16(float* d, const uint32_t* a, const uint32_t* b) {
    asm volatile(
        "mma.sync.aligned.m16n8k16.row.col.f32.bf16.bf16.f32 "
        "{%0,%1,%2,%3}, {%4,%5,%6,%7}, {%8,%9}, {%0,%1,%2,%3};"
        : "+f"(d[0]), "+f"(d[1]), "+f"(d[2]), "+f"(d[3])
        : "r"(a[0]), "r"(a[1]), "r"(a[2]), "r"(a[3]), "r"(b[0]), "r"(b[1]));
}
__device__ __forceinline__ void cp_async16(uint32_t dst, const void* src) {
    asm volatile("cp.async.cg.shared.global [%0], [%1], 16;" :: "r"(dst), "l"(src));
}
__device__ __forceinline__ void cp_commit() {
    asm volatile("cp.async.commit_group;" ::: "memory");
}
__device__ __forceinline__ void cp_wait0() {
    asm volatile("cp.async.wait_group 0;" ::: "memory");
}
__device__ __forceinline__ void cp_wait1() {
    asm volatile("cp.async.wait_group 1;" ::: "memory");
}
__device__ __forceinline__ void pack4(const float* v, uint32_t* ph, uint32_t* pl) {
#pragma unroll
    for (int q = 0; q < 4; q++) {
        uint32_t ua = __float_as_uint(v[2 * q]);
        uint32_t ub = __float_as_uint(v[2 * q + 1]);
        float ta = __uint_as_float(ua & 0xffff0000u);
        float tb = __uint_as_float(ub & 0xffff0000u);
        ph[q] = __byte_perm(ua, ub, 0x7632);
        pl[q] = __byte_perm(__float_as_uint(v[2 * q] - ta),
                            __float_as_uint(v[2 * q + 1] - tb), 0x7632);
    }
}

// ---------------------------------------------------------------------------
// SMEM layout (main kernel): A ring x3, B ring x3, params
// ---------------------------------------------------------------------------
#define SM_A     0        // 3 x 40960
#define SM_B     122880   // 3 x 20480
#define SM_IDXA  184320
#define SM_IDXB  188928
#define SM_WQ    193536
#define DYN_SMEM 211968

// om kernel smem: A 2x5120, B 2x20480
#define OM_A     0
#define OM_B     10240
#define OM_SMEM  51200

// ---------------------------------------------------------------------------
// Kernel 1a: pack main weights into bf16 hi/lo padded tiles
// ---------------------------------------------------------------------------
__global__ void prep_w_kernel(const float* __restrict__ weight) {
    int i = blockIdx.x * 256 + threadIdx.x;   // 0 .. 589823
    int chunk = i >> 13;
    int rem   = i & 8191;
    int o     = rem >> 5;
    int kl    = rem & 31;
    int kk = chunk >> 3;
    int cg = chunk & 7;
    int c  = cg * 32 + kl;
    float w = weight[o * KTOT + c * 9 + kk];
    __nv_bfloat16 hi = __float2bfloat16(w);
    __nv_bfloat16 lo = __float2bfloat16(w - __bfloat162float(hi));
    __nv_bfloat16* base = (__nv_bfloat16*)g_wA + (size_t)chunk * 20480;
    base[o * KPAD + kl]         = hi;
    base[10240 + o * KPAD + kl] = lo;
}

// ---------------------------------------------------------------------------
// Kernel 1b: pack offset-conv weights (27 rows, padded to 32) per chunk
// ---------------------------------------------------------------------------
__global__ void prep_woff_kernel(const float* __restrict__ w_off) {
    int i = blockIdx.x * 256 + threadIdx.x;   // 0 .. 73727
    int chunk = i >> 10;
    int rem   = i & 1023;
    int j     = rem >> 5;
    int kl    = rem & 31;
    int kk = chunk >> 3;
    int cg = chunk & 7;
    float w = (j < OMCH) ? w_off[j * KTOT + (cg * 32 + kl) * 9 + kk] : 0.f;
    __nv_bfloat16 hi = __float2bfloat16(w);
    __nv_bfloat16 lo = __float2bfloat16(w - __bfloat162float(hi));
    __nv_bfloat16* base = g_wOff + (size_t)chunk * 2560;
    base[j * KPAD + kl]        = hi;
    base[1280 + j * KPAD + kl] = lo;
}

// ---------------------------------------------------------------------------
// Kernel 2: offset conv as tensor GEMM. M=32 (27 used) x N=128 px per CTA.
// 128 CTAs x 256 threads = 8 warps, warp tile 32x16.
// B tile = statically shifted x (coalesced, bounds-masked), bf16 hi/lo.
// ---------------------------------------------------------------------------
__global__ __launch_bounds__(256, 1) void om_mma_kernel(
    const float* __restrict__ x, const float* __restrict__ bo)
{
    extern __shared__ char smem[];
    uint32_t sb = s2u(smem);

    const int t    = threadIdx.x;
    const int lane = t & 31;
    const int nw   = t >> 5;            // warp id 0..7 -> cols nw*16
    const int pbase = blockIdx.x * 128;
    const int b     = pbase >> 12;
    const int pib   = pbase & 4095;
    const int nloc  = t & 127;          // pixel
    const int klq   = t >> 7;           // 0/1: 16-channel half
    const int ph_   = (pib + nloc) >> 6;
    const int pw_   = (pib + nloc) & 63;

    const float* xb = x + ((size_t)b << 20);

    float acc[2][2][4];
#pragma unroll
    for (int i = 0; i < 2; i++)
#pragma unroll
        for (int j = 0; j < 2; j++)
#pragma unroll
            for (int q = 0; q < 4; q++) acc[i][j][q] = 0.f;

    const uint32_t a_off = (uint32_t)((lane & 15) * 80 + ((lane >> 4) << 4));
    const uint32_t b_off = (uint32_t)((((lane >> 4) << 3) + (lane & 7)) * 80
                                      + (((lane >> 3) & 1) << 4));
    const uint32_t bstore = (uint32_t)(nloc * 80 + klq * 32);

    // build B(chunk) values into v[16]
    auto buildB = [&](int c, float* v) {
        int kk = c >> 3, cg = c & 7;
        int kh = kk / 3, kw = kk - 3 * kh;
        int y  = ph_ + kh - 1;
        int xx = pw_ + kw - 1;
        bool ok = ((unsigned)y < 64u) && ((unsigned)xx < 64u);
        const float* xc = xb + ((size_t)(cg * 32 + klq * 16) << 12) + (y << 6) + xx;
#pragma unroll
        for (int j = 0; j < 16; j++)
            v[j] = ok ? __ldg(xc + ((size_t)j << 12)) : 0.f;
    };

    uint32_t ph[8], pl[8];

    // ---- prologue: A(0) cp.async; B(0) built ----
    {
        for (int r = 0; r < 2; r++) {
            int idx = t + (r << 8);
            if (idx < 320)
                cp_async16(sb + OM_A + (uint32_t)(idx << 4), (const char*)g_wOff + (idx << 4));
        }
        cp_commit();
        float v[16];
        buildB(0, v);
        pack4(v, ph, pl);
        pack4(v + 8, ph + 4, pl + 4);
    }

    for (int c = 0; c < NCH; c++) {
        const int buf = c & 1;

        // STS B(c)
        {
            char* bh = smem + OM_B + buf * 20480 + bstore;
            *(float4*)bh                = *(float4*)(ph + 0);
            *(float4*)(bh + 16)         = *(float4*)(ph + 4);
            *(float4*)(bh + 10240)      = *(float4*)(pl + 0);
            *(float4*)(bh + 10240 + 16) = *(float4*)(pl + 4);
        }
        cp_wait0();
        __syncthreads();

        const bool pf = (c + 1 < NCH);
        if (pf) {
            const char* srcA = (const char*)(g_wOff + (size_t)(c + 1) * 2560);
            uint32_t dA = sb + OM_A + (buf ^ 1) * 5120;
            for (int r = 0; r < 2; r++) {
                int idx = t + (r << 8);
                if (idx < 320)
                    cp_async16(dA + (uint32_t)(idx << 4), srcA + (idx << 4));
            }
            cp_commit();
        }

        float v[16];
        if (pf) buildB(c + 1, v);    // LDGs in flight over the MMA burst

        const uint32_t A0 = sb + OM_A + buf * 5120;
        const uint32_t B0 = sb + OM_B + buf * 20480;
#pragma unroll
        for (int pass = 0; pass < 3; pass++) {
            uint32_t Ab = A0 + (pass == 2 ? 2560u : 0u);
            uint32_t Bb = B0 + (pass == 1 ? 10240u : 0u);
#pragma unroll
            for (int h = 0; h < 2; h++) {
                uint32_t af[2][4], bfr[4];
#pragma unroll
                for (int mi = 0; mi < 2; mi++)
                    ldsm4(af[mi], Ab + a_off + (uint32_t)((mi * 16) * 80 + h * 32));
                ldsm4(bfr, Bb + b_off + (uint32_t)((nw * 16) * 80 + h * 32));
#pragma unroll
                for (int mi = 0; mi < 2; mi++) {
                    mma_bf16(acc[mi][0], af[mi], &bfr[0]);
                    mma_bf16(acc[mi][1], af[mi], &bfr[2]);
                }
            }
        }
        if (pf) {
            pack4(v, ph, pl);
            pack4(v + 8, ph + 4, pl + 4);
        }
    }

    // ---- epilogue: rows j<27 -> g_om (+bias) ----
#pragma unroll
    for (int mi = 0; mi < 2; mi++) {
#pragma unroll
        for (int half = 0; half < 2; half++) {
            int j = mi * 16 + (lane >> 2) + half * 8;
            if (j < OMCH) {
                float bv = __ldg(bo + j);
                float* row = g_om + (((size_t)(b * OMCH + j)) << 12) + pib;
#pragma unroll
                for (int nj = 0; nj < 2; nj++) {
                    int cc = nw * 16 + nj * 8 + ((lane & 3) << 1);
                    row[cc]     = acc[mi][nj][2 * half]     + bv;
                    row[cc + 1] = acc[mi][nj][2 * half + 1] + bv;
                }
            }
        }
    }
}

// ---------------------------------------------------------------------------
// Kernel 3: fused bilinear-sample + bf16 3-pass mma.sync GEMM (unchanged R8).
// ---------------------------------------------------------------------------
struct GatherCtx {
    int i00, i01, i10, i11;
    float4 wq;
    const float* xch;
};

__device__ __forceinline__ void gather_issue(const GatherCtx& g, int grp, float* r) {
    const float* xc0 = g.xch + ((size_t)(2 * grp) << 12);
    const float* xc1 = xc0 + 4096;
    r[0] = __ldg(xc0 + g.i00); r[1] = __ldg(xc0 + g.i01);
    r[2] = __ldg(xc0 + g.i10); r[3] = __ldg(xc0 + g.i11);
    r[4] = __ldg(xc1 + g.i00); r[5] = __ldg(xc1 + g.i01);
    r[6] = __ldg(xc1 + g.i10); r[7] = __ldg(xc1 + g.i11);
}
__device__ __forceinline__ void gather_combine(const GatherCtx& g, const float* r,
                                               float& v0, float& v1) {
    v0 = g.wq.x * r[0] + g.wq.y * r[1] + g.wq.z * r[2] + g.wq.w * r[3];
    v1 = g.wq.x * r[4] + g.wq.y * r[5] + g.wq.z * r[6] + g.wq.w * r[7];
}

__device__ __forceinline__ void mma_subpass(uint32_t Ab, uint32_t Bb,
                                            uint32_t a_off, uint32_t b_off,
                                            int mw, int nw, int h,
                                            float (*acc)[4][4]) {
    uint32_t af[4][4], bfr[2][4];
#pragma unroll
    for (int mi = 0; mi < 4; mi++)
        ldsm4(af[mi], Ab + a_off + (uint32_t)((mw * 64 + mi * 16) * 80 + h * 32));
#pragma unroll
    for (int p = 0; p < 2; p++)
        ldsm4(bfr[p], Bb + b_off + (uint32_t)((nw * 32 + p * 16) * 80 + h * 32));
#pragma unroll
    for (int mi = 0; mi < 4; mi++)
#pragma unroll
        for (int p = 0; p < 2; p++) {
            mma_bf16(acc[mi][2 * p],     af[mi], &bfr[p][0]);
            mma_bf16(acc[mi][2 * p + 1], af[mi], &bfr[p][2]);
        }
}

__global__ __launch_bounds__(512, 1) void dcn_mma_kernel(
    const float* __restrict__ x, const float* __restrict__ bias,
    float* __restrict__ out)
{
    extern __shared__ char smem[];
    uint32_t sb = s2u(smem);

    const int t    = threadIdx.x;
    const int lane = t & 31;
    const int wid  = t >> 5;
    const int mw   = wid >> 2;
    const int nw   = wid & 3;
    const int pbase = blockIdx.x * 128;
    const int b     = pbase >> 12;
    const int pib   = pbase & 4095;

    uint32_t* s_idxA = (uint32_t*)(smem + SM_IDXA);
    uint32_t* s_idxB = (uint32_t*)(smem + SM_IDXB);
    float4*   s_wq   = (float4*)(smem + SM_WQ);

    // ---- sampling params: 9 kk x 128 pixels ----
    for (int e = t; e < KK_ * 128; e += 512) {
        int kk = e >> 7;
        int n  = e & 127;
        int pimg = pib + n;
        int h = pimg >> 6, w = pimg & 63;
        const float* omb = g_om + (((size_t)b * OMCH) << 12) + pimg;
        float dy = omb[(size_t)(2 * kk) << 12];
        float dx = omb[(size_t)(2 * kk + 1) << 12];
        float mv = omb[(size_t)(18 + kk) << 12];
        float m  = 1.0f / (1.0f + expf(-mv));
        int kh = kk / 3, kw = kk - 3 * kh;
        float py = (float)(h - 1 + kh) + dy;
        float px = (float)(w - 1 + kw) + dx;
        float y0f = floorf(py), x0f = floorf(px);
        float ly = py - y0f, lx = px - x0f;
        int y0 = (int)y0f, x0 = (int)x0f;
        int y1 = y0 + 1, x1 = x0 + 1;
        float vy0 = ((unsigned)y0 < 64u) ? 1.f : 0.f;
        float vy1 = ((unsigned)y1 < 64u) ? 1.f : 0.f;
        float vx0 = ((unsigned)x0 < 64u) ? 1.f : 0.f;
        float vx1 = ((unsigned)x1 < 64u) ? 1.f : 0.f;
        int y0c = min(max(y0, 0), 63), y1c = min(max(y1, 0), 63);
        int x0c = min(max(x0, 0), 63), x1c = min(max(x1, 0), 63);
        float w00 = (1.f - ly) * (1.f - lx) * m * vy0 * vx0;
        float w01 = (1.f - ly) * lx * m * vy0 * vx1;
        float w10 = ly * (1.f - lx) * m * vy1 * vx0;
        float w11 = ly * lx * m * vy1 * vx1;
        s_idxA[e] = (uint32_t)(y0c * 64 + x0c) | ((uint32_t)(y0c * 64 + x1c) << 16);
        s_idxB[e] = (uint32_t)(y1c * 64 + x0c) | ((uint32_t)(y1c * 64 + x1c) << 16);
        s_wq[e] = make_float4(w00, w01, w10, w11);
    }

    float acc[4][4][4];
#pragma unroll
    for (int i = 0; i < 4; i++)
#pragma unroll
        for (int j = 0; j < 4; j++)
#pragma unroll
            for (int q = 0; q < 4; q++) acc[i][j][q] = 0.f;

    const uint32_t a_off = (uint32_t)((lane & 15) * 80 + ((lane >> 4) << 4));
    const uint32_t b_off = (uint32_t)((((lane >> 4) << 3) + (lane & 7)) * 80
                                      + (((lane >> 3) & 1) << 4));

    const float* xb = x + ((size_t)b << 20);
    const int nloc  = t & 127;
    const int klq   = t >> 7;

    auto load_ctx = [&](int c, GatherCtx& g) {
        int kk = c >> 3, cg = c & 7;
        int e  = (kk << 7) + nloc;
        uint32_t ia = s_idxA[e], ib2 = s_idxB[e];
        g.i00 = ia & 0xffff;  g.i01 = ia >> 16;
        g.i10 = ib2 & 0xffff; g.i11 = ib2 >> 16;
        g.wq  = s_wq[e];
        g.xch = xb + ((size_t)(cg * 32 + klq * 8) << 12);
    };

    const uint32_t bstore = (uint32_t)(nloc * 80 + klq * 16);

    // ---- prologue ----
    {
        const float4* srcA0 = g_wA;
        uint32_t dA0 = sb + SM_A;
#pragma unroll
        for (int r = 0; r < 5; r++)
            cp_async16(dA0 + (uint32_t)((t + (r << 9)) << 4), srcA0 + t + (r << 9));
        cp_commit();
        const float4* srcA1 = g_wA + 2560;
        uint32_t dA1 = sb + SM_A + 40960;
#pragma unroll
        for (int r = 0; r < 5; r++)
            cp_async16(dA1 + (uint32_t)((t + (r << 9)) << 4), srcA1 + t + (r << 9));
        cp_commit();

        __syncthreads();

        GatherCtx g; load_ctx(0, g);
        float v[8], r[8];
#pragma unroll
        for (int grp = 0; grp < 4; grp++) {
            gather_issue(g, grp, r);
            gather_combine(g, r, v[2 * grp], v[2 * grp + 1]);
        }
        uint32_t ph[4], pl[4];
        pack4(v, ph, pl);
        char* bh = smem + SM_B + bstore;
        *(float4*)bh           = *(float4*)ph;
        *(float4*)(bh + 10240) = *(float4*)pl;

        cp_wait1();
        __syncthreads();
    }

    int cb = 0;
    for (int c = 0; c < NCH; c++) {
        const int nb = (cb == 2) ? 0 : cb + 1;
        const int pb = (nb == 2) ? 0 : nb + 1;

        const uint32_t Ah0 = sb + SM_A + cb * 40960;
        const uint32_t Al0 = Ah0 + 20480;
        const uint32_t Bh0 = sb + SM_B + cb * 20480;
        const uint32_t Bl0 = Bh0 + 10240;

        const bool pf = (c + 1 < NCH);
        GatherCtx g;
        float v[8], r[8];
        if (pf) { load_ctx(c + 1, g); gather_issue(g, 0, r); }

        mma_subpass(Ah0, Bh0, a_off, b_off, mw, nw, 0, acc);
        if (pf) { gather_combine(g, r, v[0], v[1]); gather_issue(g, 1, r); }
        mma_subpass(Ah0, Bh0, a_off, b_off, mw, nw, 1, acc);
        if (pf) { gather_combine(g, r, v[2], v[3]); gather_issue(g, 2, r); }
        mma_subpass(Ah0, Bl0, a_off, b_off, mw, nw, 0, acc);
        if (pf) { gather_combine(g, r, v[4], v[5]); gather_issue(g, 3, r); }
        mma_subpass(Ah0, Bl0, a_off, b_off, mw, nw, 1, acc);
        if (pf) {
            gather_combine(g, r, v[6], v[7]);
            uint32_t ph[4], pl[4];
            pack4(v, ph, pl);
            char* bh = smem + SM_B + nb * 20480 + bstore;
            *(float4*)bh           = *(float4*)ph;
            *(float4*)(bh + 10240) = *(float4*)pl;
        }
        if (c + 2 < NCH) {
            const float4* srcA = g_wA + (size_t)(c + 2) * 2560;
            uint32_t dA = sb + SM_A + pb * 40960;
#pragma unroll
            for (int rr = 0; rr < 5; rr++)
                cp_async16(dA + (uint32_t)((t + (rr << 9)) << 4), srcA + t + (rr << 9));
            cp_commit();
        }
        mma_subpass(Al0, Bh0, a_off, b_off, mw, nw, 0, acc);
        mma_subpass(Al0, Bh0, a_off, b_off, mw, nw, 1, acc);

        if (c + 2 < NCH) cp_wait1();
        else             cp_wait0();
        __syncthreads();
        cb = nb;
    }

    // ---- epilogue ----
    const int m0   = mw * 64 + (lane >> 2);
    const int col0 = nw * 32 + ((lane & 3) << 1);
#pragma unroll
    for (int mi = 0; mi < 4; mi++) {
        int o = m0 + mi * 16;
        float bv0 = __ldg(bias + o);
        float bv1 = __ldg(bias + o + 8);
        float* r0 = out + (((size_t)(b * O_ + o)) << 12) + pib;
        float* r1 = r0 + (8 << 12);
#pragma unroll
        for (int nj = 0; nj < 4; nj++) {
            int cc = col0 + nj * 8;
            float2 v0 = make_float2(acc[mi][nj][0] + bv0, acc[mi][nj][1] + bv0);
            float2 v1 = make_float2(acc[mi][nj][2] + bv1, acc[mi][nj][3] + bv1);
            *(float2*)(r0 + cc) = v0;
            *(float2*)(r1 + cc) = v1;
        }
    }
}

// ---------------------------------------------------------------------------
// Launch
// ---------------------------------------------------------------------------
extern "C" void kernel_launch(void* const* d_in, const int* in_sizes, int n_in,
                              void* d_out, int out_size)
{
    const float* x      = (const float*)d_in[0];
    const float* w_off  = (const float*)d_in[1];
    const float* b_off  = (const float*)d_in[2];
    const float* weight = (const float*)d_in[3];
    const float* bias   = (const float*)d_in[4];
    float* out = (float*)d_out;

    cudaFuncSetAttribute(dcn_mma_kernel,
                         cudaFuncAttributeMaxDynamicSharedMemorySize, DYN_SMEM);
    cudaFuncSetAttribute(om_mma_kernel,
                         cudaFuncAttributeMaxDynamicSharedMemorySize, OM_SMEM);

    prep_w_kernel<<<2304, 256>>>(weight);
    prep_woff_kernel<<<288, 256>>>(w_off);
    om_mma_kernel<<<128, 256, OM_SMEM>>>(x, b_off);
    dcn_mma_kernel<<<NPIX / 128, 512, DYN_SMEM>>>(x, bias, out);
}

// round 10
// speedup vs baseline: 1.2145x; 1.0077x over previous
#include <cuda_runtime.h>
#include <cuda_bf16.h>
#include <cstdint>

// Problem constants
#define B_    4
#define C_    256
#define H_    64
#define W_    64
#define O_    256
#define KK_   9
#define HW_   4096
#define NPIX  16384
#define KTOT  2304
#define OMCH  27
#define OMSZ  (B_*OMCH*HW_)   // 442368

// GEMM chunking: k' = kk*256 + c; 72 chunks of 32 channels
#define NCH   72
#define KPAD  40              // padded K row -> 80B rows, conflict-free ldmatrix/STS.128

// Device scratch
__device__ float  g_om[OMSZ];
// main GEMM weights: per chunk [hi 256x40 bf16][lo 256x40 bf16] = 40960 B
__device__ float4 g_wA[NCH * 2560];
// offset-conv weights: per chunk [hi 32x40 bf16][lo 32x40 bf16] = 5120 B
__device__ __nv_bfloat16 g_wOff[NCH * 2560];

// ---------------------------------------------------------------------------
// PTX helpers
// ---------------------------------------------------------------------------
__device__ __forceinline__ uint32_t s2u(const void* p) {
    uint32_t r;
    asm("{ .reg .u64 t; cvta.to.shared.u64 t, %1; cvt.u32.u64 %0, t; }" : "=r"(r) : "l"(p));
    return r;
}
__device__ __forceinline__ void ldsm4(uint32_t* r, uint32_t addr) {
    asm volatile("ldmatrix.sync.aligned.m8n8.x4.shared.b16 {%0,%1,%2,%3}, [%4];"
                 : "=r"(r[0]), "=r"(r[1]), "=r"(r[2]), "=r"(r[3]) : "r"(addr));
}
__device__ __forceinline__ void mma_bf16(float* d, const uint32_t* a, const uint32_t* b) {
    asm volatile(
        "mma.sync.aligned.m16n8k16.row.col.f32.bf16.bf16.f32 "
        "{%0,%1,%2,%3}, {%4,%5,%6,%7}, {%8,%9}, {%0,%1,%2,%3};"
        : "+f"(d[0]), "+f"(d[1]), "+f"(d[2]), "+f"(d[3])
        : "r"(a[0]), "r"(a[1]), "r"(a[2]), "r"(a[3]), "r"(b[0]), "r"(b[1]));
}
__device__ __forceinline__ void cp_async16(uint32_t dst, const void* src) {
    asm volatile("cp.async.cg.shared.global [%0], [%1], 16;" :: "r"(dst), "l"(src));
}
__device__ __forceinline__ void cp_commit() {
    asm volatile("cp.async.commit_group;" ::: "memory");
}
__device__ __forceinline__ void cp_wait0() {
    asm volatile("cp.async.wait_group 0;" ::: "memory");
}
__device__ __forceinline__ void cp_wait1() {
    asm volatile("cp.async.wait_group 1;" ::: "memory");
}
__device__ __forceinline__ void pack4(const float* v, uint32_t* ph, uint32_t* pl) {
#pragma unroll
    for (int q = 0; q < 4; q++) {
        uint32_t ua = __float_as_uint(v[2 * q]);
        uint32_t ub = __float_as_uint(v[2 * q + 1]);
        float ta = __uint_as_float(ua & 0xffff0000u);
        float tb = __uint_as_float(ub & 0xffff0000u);
        ph[q] = __byte_perm(ua, ub, 0x7632);
        pl[q] = __byte_perm(__float_as_uint(v[2 * q] - ta),
                            __float_as_uint(v[2 * q + 1] - tb), 0x7632);
    }
}

// ---------------------------------------------------------------------------
// SMEM layout (main kernel): A ring x3, B ring x3, params
// ---------------------------------------------------------------------------
#define SM_A     0        // 3 x 40960
#define SM_B     122880   // 3 x 20480
#define SM_IDXA  184320
#define SM_IDXB  188928
#define SM_WQ    193536
#define DYN_SMEM 211968

// om kernel smem: A 2x5120, B 2x20480
#define OM_A     0
#define OM_B     10240
#define OM_SMEM  51200

// ---------------------------------------------------------------------------
// Kernel 1a: pack main weights into bf16 hi/lo padded tiles
// ---------------------------------------------------------------------------
__global__ void prep_w_kernel(const float* __restrict__ weight) {
    int i = blockIdx.x * 256 + threadIdx.x;   // 0 .. 589823
    int chunk = i >> 13;
    int rem   = i & 8191;
    int o     = rem >> 5;
    int kl    = rem & 31;
    int kk = chunk >> 3;
    int cg = chunk & 7;
    int c  = cg * 32 + kl;
    float w = weight[o * KTOT + c * 9 + kk];
    __nv_bfloat16 hi = __float2bfloat16(w);
    __nv_bfloat16 lo = __float2bfloat16(w - __bfloat162float(hi));
    __nv_bfloat16* base = (__nv_bfloat16*)g_wA + (size_t)chunk * 20480;
    base[o * KPAD + kl]         = hi;
    base[10240 + o * KPAD + kl] = lo;
}

// ---------------------------------------------------------------------------
// Kernel 1b: pack offset-conv weights (27 rows, padded to 32) per chunk
// ---------------------------------------------------------------------------
__global__ void prep_woff_kernel(const float* __restrict__ w_off) {
    int i = blockIdx.x * 256 + threadIdx.x;   // 0 .. 73727
    int chunk = i >> 10;
    int rem   = i & 1023;
    int j     = rem >> 5;
    int kl    = rem & 31;
    int kk = chunk >> 3;
    int cg = chunk & 7;
    float w = (j < OMCH) ? w_off[j * KTOT + (cg * 32 + kl) * 9 + kk] : 0.f;
    __nv_bfloat16 hi = __float2bfloat16(w);
    __nv_bfloat16 lo = __float2bfloat16(w - __bfloat162float(hi));
    __nv_bfloat16* base = g_wOff + (size_t)chunk * 2560;
    base[j * KPAD + kl]        = hi;
    base[1280 + j * KPAD + kl] = lo;
}

// ---------------------------------------------------------------------------
// Kernel 2: offset conv as tensor GEMM (unchanged R9).
// ---------------------------------------------------------------------------
__global__ __launch_bounds__(256, 1) void om_mma_kernel(
    const float* __restrict__ x, const float* __restrict__ bo)
{
    extern __shared__ char smem[];
    uint32_t sb = s2u(smem);

    const int t    = threadIdx.x;
    const int lane = t & 31;
    const int nw   = t >> 5;            // warp id 0..7 -> cols nw*16
    const int pbase = blockIdx.x * 128;
    const int b     = pbase >> 12;
    const int pib   = pbase & 4095;
    const int nloc  = t & 127;          // pixel
    const int klq   = t >> 7;           // 0/1: 16-channel half
    const int ph_   = (pib + nloc) >> 6;
    const int pw_   = (pib + nloc) & 63;

    const float* xb = x + ((size_t)b << 20);

    float acc[2][2][4];
#pragma unroll
    for (int i = 0; i < 2; i++)
#pragma unroll
        for (int j = 0; j < 2; j++)
#pragma unroll
            for (int q = 0; q < 4; q++) acc[i][j][q] = 0.f;

    const uint32_t a_off = (uint32_t)((lane & 15) * 80 + ((lane >> 4) << 4));
    const uint32_t b_off = (uint32_t)((((lane >> 4) << 3) + (lane & 7)) * 80
                                      + (((lane >> 3) & 1) << 4));
    const uint32_t bstore = (uint32_t)(nloc * 80 + klq * 32);

    auto buildB = [&](int c, float* v) {
        int kk = c >> 3, cg = c & 7;
        int kh = kk / 3, kw = kk - 3 * kh;
        int y  = ph_ + kh - 1;
        int xx = pw_ + kw - 1;
        bool ok = ((unsigned)y < 64u) && ((unsigned)xx < 64u);
        const float* xc = xb + ((size_t)(cg * 32 + klq * 16) << 12) + (y << 6) + xx;
#pragma unroll
        for (int j = 0; j < 16; j++)
            v[j] = ok ? __ldg(xc + ((size_t)j << 12)) : 0.f;
    };

    uint32_t ph[8], pl[8];

    // ---- prologue: A(0) cp.async; B(0) built ----
    {
        for (int r = 0; r < 2; r++) {
            int idx = t + (r << 8);
            if (idx < 320)
                cp_async16(sb + OM_A + (uint32_t)(idx << 4), (const char*)g_wOff + (idx << 4));
        }
        cp_commit();
        float v[16];
        buildB(0, v);
        pack4(v, ph, pl);
        pack4(v + 8, ph + 4, pl + 4);
    }

    for (int c = 0; c < NCH; c++) {
        const int buf = c & 1;

        {
            char* bh = smem + OM_B + buf * 20480 + bstore;
            *(float4*)bh                = *(float4*)(ph + 0);
            *(float4*)(bh + 16)         = *(float4*)(ph + 4);
            *(float4*)(bh + 10240)      = *(float4*)(pl + 0);
            *(float4*)(bh + 10240 + 16) = *(float4*)(pl + 4);
        }
        cp_wait0();
        __syncthreads();

        const bool pf = (c + 1 < NCH);
        if (pf) {
            const char* srcA = (const char*)(g_wOff + (size_t)(c + 1) * 2560);
            uint32_t dA = sb + OM_A + (buf ^ 1) * 5120;
            for (int r = 0; r < 2; r++) {
                int idx = t + (r << 8);
                if (idx < 320)
                    cp_async16(dA + (uint32_t)(idx << 4), srcA + (idx << 4));
            }
            cp_commit();
        }

        float v[16];
        if (pf) buildB(c + 1, v);

        const uint32_t A0 = sb + OM_A + buf * 5120;
        const uint32_t B0 = sb + OM_B + buf * 20480;
#pragma unroll
        for (int pass = 0; pass < 3; pass++) {
            uint32_t Ab = A0 + (pass == 2 ? 2560u : 0u);
            uint32_t Bb = B0 + (pass == 1 ? 10240u : 0u);
#pragma unroll
            for (int h = 0; h < 2; h++) {
                uint32_t af[2][4], bfr[4];
#pragma unroll
                for (int mi = 0; mi < 2; mi++)
                    ldsm4(af[mi], Ab + a_off + (uint32_t)((mi * 16) * 80 + h * 32));
                ldsm4(bfr, Bb + b_off + (uint32_t)((nw * 16) * 80 + h * 32));
#pragma unroll
                for (int mi = 0; mi < 2; mi++) {
                    mma_bf16(acc[mi][0], af[mi], &bfr[0]);
                    mma_bf16(acc[mi][1], af[mi], &bfr[2]);
                }
            }
        }
        if (pf) {
            pack4(v, ph, pl);
            pack4(v + 8, ph + 4, pl + 4);
        }
    }

    // ---- epilogue: rows j<27 -> g_om (+bias) ----
#pragma unroll
    for (int mi = 0; mi < 2; mi++) {
#pragma unroll
        for (int half = 0; half < 2; half++) {
            int j = mi * 16 + (lane >> 2) + half * 8;
            if (j < OMCH) {
                float bv = __ldg(bo + j);
                float* row = g_om + (((size_t)(b * OMCH + j)) << 12) + pib;
#pragma unroll
                for (int nj = 0; nj < 2; nj++) {
                    int cc = nw * 16 + nj * 8 + ((lane & 3) << 1);
                    row[cc]     = acc[mi][nj][2 * half]     + bv;
                    row[cc + 1] = acc[mi][nj][2 * half + 1] + bv;
                }
            }
        }
    }
}

// ---------------------------------------------------------------------------
// Kernel 3: fused bilinear-sample + bf16 3-pass mma.sync GEMM.
// 128 CTAs x 512 threads = 16 warps (4 M x 4 N, warp tile 64x32).
// Per h-phase fragment reuse: Ah,Bh -> AhBh; Bl -> AhBl; Al -> AlBh.
// ldsm.x4 per warp per chunk: 24 (was 36).
// ---------------------------------------------------------------------------
struct GatherCtx {
    int i00, i01, i10, i11;
    float4 wq;
    const float* xch;
};

__device__ __forceinline__ void gather_issue(const GatherCtx& g, int grp, float* r) {
    const float* xc0 = g.xch + ((size_t)(2 * grp) << 12);
    const float* xc1 = xc0 + 4096;
    r[0] = __ldg(xc0 + g.i00); r[1] = __ldg(xc0 + g.i01);
    r[2] = __ldg(xc0 + g.i10); r[3] = __ldg(xc0 + g.i11);
    r[4] = __ldg(xc1 + g.i00); r[5] = __ldg(xc1 + g.i01);
    r[6] = __ldg(xc1 + g.i10); r[7] = __ldg(xc1 + g.i11);
}
__device__ __forceinline__ void gather_combine(const GatherCtx& g, const float* r,
                                               float& v0, float& v1) {
    v0 = g.wq.x * r[0] + g.wq.y * r[1] + g.wq.z * r[2] + g.wq.w * r[3];
    v1 = g.wq.x * r[4] + g.wq.y * r[5] + g.wq.z * r[6] + g.wq.w * r[7];
}

__global__ __launch_bounds__(512, 1) void dcn_mma_kernel(
    const float* __restrict__ x, const float* __restrict__ bias,
    float* __restrict__ out)
{
    extern __shared__ char smem[];
    uint32_t sb = s2u(smem);

    const int t    = threadIdx.x;
    const int lane = t & 31;
    const int wid  = t >> 5;
    const int mw   = wid >> 2;
    const int nw   = wid & 3;
    const int pbase = blockIdx.x * 128;
    const int b     = pbase >> 12;
    const int pib   = pbase & 4095;

    uint32_t* s_idxA = (uint32_t*)(smem + SM_IDXA);
    uint32_t* s_idxB = (uint32_t*)(smem + SM_IDXB);
    float4*   s_wq   = (float4*)(smem + SM_WQ);

    // ---- sampling params: 9 kk x 128 pixels ----
    for (int e = t; e < KK_ * 128; e += 512) {
        int kk = e >> 7;
        int n  = e & 127;
        int pimg = pib + n;
        int h = pimg >> 6, w = pimg & 63;
        const float* omb = g_om + (((size_t)b * OMCH) << 12) + pimg;
        float dy = omb[(size_t)(2 * kk) << 12];
        float dx = omb[(size_t)(2 * kk + 1) << 12];
        float mv = omb[(size_t)(18 + kk) << 12];
        float m  = 1.0f / (1.0f + expf(-mv));
        int kh = kk / 3, kw = kk - 3 * kh;
        float py = (float)(h - 1 + kh) + dy;
        float px = (float)(w - 1 + kw) + dx;
        float y0f = floorf(py), x0f = floorf(px);
        float ly = py - y0f, lx = px - x0f;
        int y0 = (int)y0f, x0 = (int)x0f;
        int y1 = y0 + 1, x1 = x0 + 1;
        float vy0 = ((unsigned)y0 < 64u) ? 1.f : 0.f;
        float vy1 = ((unsigned)y1 < 64u) ? 1.f : 0.f;
        float vx0 = ((unsigned)x0 < 64u) ? 1.f : 0.f;
        float vx1 = ((unsigned)x1 < 64u) ? 1.f : 0.f;
        int y0c = min(max(y0, 0), 63), y1c = min(max(y1, 0), 63);
        int x0c = min(max(x0, 0), 63), x1c = min(max(x1, 0), 63);
        float w00 = (1.f - ly) * (1.f - lx) * m * vy0 * vx0;
        float w01 = (1.f - ly) * lx * m * vy0 * vx1;
        float w10 = ly * (1.f - lx) * m * vy1 * vx0;
        float w11 = ly * lx * m * vy1 * vx1;
        s_idxA[e] = (uint32_t)(y0c * 64 + x0c) | ((uint32_t)(y0c * 64 + x1c) << 16);
        s_idxB[e] = (uint32_t)(y1c * 64 + x0c) | ((uint32_t)(y1c * 64 + x1c) << 16);
        s_wq[e] = make_float4(w00, w01, w10, w11);
    }

    float acc[4][4][4];
#pragma unroll
    for (int i = 0; i < 4; i++)
#pragma unroll
        for (int j = 0; j < 4; j++)
#pragma unroll
            for (int q = 0; q < 4; q++) acc[i][j][q] = 0.f;

    const uint32_t a_off = (uint32_t)((lane & 15) * 80 + ((lane >> 4) << 4));
    const uint32_t b_off = (uint32_t)((((lane >> 4) << 3) + (lane & 7)) * 80
                                      + (((lane >> 3) & 1) << 4));

    const float* xb = x + ((size_t)b << 20);
    const int nloc  = t & 127;
    const int klq   = t >> 7;

    auto load_ctx = [&](int c, GatherCtx& g) {
        int kk = c >> 3, cg = c & 7;
        int e  = (kk << 7) + nloc;
        uint32_t ia = s_idxA[e], ib2 = s_idxB[e];
        g.i00 = ia & 0xffff;  g.i01 = ia >> 16;
        g.i10 = ib2 & 0xffff; g.i11 = ib2 >> 16;
        g.wq  = s_wq[e];
        g.xch = xb + ((size_t)(cg * 32 + klq * 8) << 12);
    };

    auto loadA = [&](uint32_t base, int h, uint32_t (*f)[4]) {
#pragma unroll
        for (int mi = 0; mi < 4; mi++)
            ldsm4(f[mi], base + a_off + (uint32_t)((mw * 64 + mi * 16) * 80 + h * 32));
    };
    auto loadB = [&](uint32_t base, int h, uint32_t (*f)[4]) {
#pragma unroll
        for (int p = 0; p < 2; p++)
            ldsm4(f[p], base + b_off + (uint32_t)((nw * 32 + p * 16) * 80 + h * 32));
    };
    auto mma_block = [&](uint32_t (*af)[4], uint32_t (*bf)[4]) {
#pragma unroll
        for (int mi = 0; mi < 4; mi++)
#pragma unroll
            for (int p = 0; p < 2; p++) {
                mma_bf16(acc[mi][2 * p],     af[mi], &bf[p][0]);
                mma_bf16(acc[mi][2 * p + 1], af[mi], &bf[p][2]);
            }
    };

    const uint32_t bstore = (uint32_t)(nloc * 80 + klq * 16);

    // ---- prologue ----
    {
        const float4* srcA0 = g_wA;
        uint32_t dA0 = sb + SM_A;
#pragma unroll
        for (int r = 0; r < 5; r++)
            cp_async16(dA0 + (uint32_t)((t + (r << 9)) << 4), srcA0 + t + (r << 9));
        cp_commit();
        const float4* srcA1 = g_wA + 2560;
        uint32_t dA1 = sb + SM_A + 40960;
#pragma unroll
        for (int r = 0; r < 5; r++)
            cp_async16(dA1 + (uint32_t)((t + (r << 9)) << 4), srcA1 + t + (r << 9));
        cp_commit();

        __syncthreads();

        GatherCtx g; load_ctx(0, g);
        float v[8], r[8];
#pragma unroll
        for (int grp = 0; grp < 4; grp++) {
            gather_issue(g, grp, r);
            gather_combine(g, r, v[2 * grp], v[2 * grp + 1]);
        }
        uint32_t ph[4], pl[4];
        pack4(v, ph, pl);
        char* bh = smem + SM_B + bstore;
        *(float4*)bh           = *(float4*)ph;
        *(float4*)(bh + 10240) = *(float4*)pl;

        cp_wait1();
        __syncthreads();
    }

    int cb = 0;
    for (int c = 0; c < NCH; c++) {
        const int nb = (cb == 2) ? 0 : cb + 1;
        const int pb = (nb == 2) ? 0 : nb + 1;

        const uint32_t Ah0 = sb + SM_A + cb * 40960;
        const uint32_t Al0 = Ah0 + 20480;
        const uint32_t Bh0 = sb + SM_B + cb * 20480;
        const uint32_t Bl0 = Bh0 + 10240;

        const bool pf = (c + 1 < NCH);
        GatherCtx g;
        float v[8], r[8];
        if (pf) { load_ctx(c + 1, g); gather_issue(g, 0, r); }

        uint32_t afh[4][4], afl[4][4], bfh[2][4], bfl[2][4];

        // ---- h = 0: Ah,Bh -> AhBh; Bl -> AhBl; Al -> AlBh ----
        loadA(Ah0, 0, afh); loadB(Bh0, 0, bfh);
        mma_block(afh, bfh);
        if (pf) { gather_combine(g, r, v[0], v[1]); gather_issue(g, 1, r); }
        loadB(Bl0, 0, bfl);
        mma_block(afh, bfl);
        if (pf) { gather_combine(g, r, v[2], v[3]); gather_issue(g, 2, r); }
        loadA(Al0, 0, afl);
        mma_block(afl, bfh);
        if (pf) { gather_combine(g, r, v[4], v[5]); gather_issue(g, 3, r); }

        // ---- h = 1: same pattern ----
        loadA(Ah0, 1, afh); loadB(Bh0, 1, bfh);
        mma_block(afh, bfh);
        if (pf) {
            gather_combine(g, r, v[6], v[7]);
            uint32_t ph[4], pl[4];
            pack4(v, ph, pl);
            char* bh = smem + SM_B + nb * 20480 + bstore;
            *(float4*)bh           = *(float4*)ph;
            *(float4*)(bh + 10240) = *(float4*)pl;
        }
        if (c + 2 < NCH) {
            const float4* srcA = g_wA + (size_t)(c + 2) * 2560;
            uint32_t dA = sb + SM_A + pb * 40960;
#pragma unroll
            for (int rr = 0; rr < 5; rr++)
                cp_async16(dA + (uint32_t)((t + (rr << 9)) << 4), srcA + t + (rr << 9));
            cp_commit();
        }
        loadB(Bl0, 1, bfl);
        mma_block(afh, bfl);
        loadA(Al0, 1, afl);
        mma_block(afl, bfh);

        if (c + 2 < NCH) cp_wait1();
        else             cp_wait0();
        __syncthreads();
        cb = nb;
    }

    // ---- epilogue ----
    const int m0   = mw * 64 + (lane >> 2);
    const int col0 = nw * 32 + ((lane & 3) << 1);
#pragma unroll
    for (int mi = 0; mi < 4; mi++) {
        int o = m0 + mi * 16;
        float bv0 = __ldg(bias + o);
        float bv1 = __ldg(bias + o + 8);
        float* r0 = out + (((size_t)(b * O_ + o)) << 12) + pib;
        float* r1 = r0 + (8 << 12);
#pragma unroll
        for (int nj = 0; nj < 4; nj++) {
            int cc = col0 + nj * 8;
            float2 v0 = make_float2(acc[mi][nj][0] + bv0, acc[mi][nj][1] + bv0);
            float2 v1 = make_float2(acc[mi][nj][2] + bv1, acc[mi][nj][3] + bv1);
            *(float2*)(r0 + cc) = v0;
            *(float2*)(r1 + cc) = v1;
        }
    }
}

// ---------------------------------------------------------------------------
// Launch
// ---------------------------------------------------------------------------
extern "C" void kernel_launch(void* const* d_in, const int* in_sizes, int n_in,
                              void* d_out, int out_size)
{
    const float* x      = (const float*)d_in[0];
    const float* w_off  = (const float*)d_in[1];
    const float* b_off  = (const float*)d_in[2];
    const float* weight = (const float*)d_in[3];
    const float* bias   = (const float*)d_in[4];
    float* out = (float*)d_out;

    cudaFuncSetAttribute(dcn_mma_kernel,
                         cudaFuncAttributeMaxDynamicSharedMemorySize, DYN_SMEM);
    cudaFuncSetAttribute(om_mma_kernel,
                         cudaFuncAttributeMaxDynamicSharedMemorySize, OM_SMEM);

    prep_w_kernel<<<2304, 256>>>(weight);
    prep_woff_kernel<<<288, 256>>>(w_off);
    om_mma_kernel<<<128, 256, OM_SMEM>>>(x, b_off);
    dcn_mma_kernel<<<NPIX / 128, 512, DYN_SMEM>>>(x, bias, out);
}